// round 5
// baseline (speedup 1.0000x reference)
#include <cuda_runtime.h>
#include <math.h>
#include <stdint.h>

#define NT      64             // threads per block
#define EPB     128            // batch elements per block (2 per thread)
#define NB      512            // 65536 / EPB
#define TSTEPS  128
#define TT      8              // timesteps per tile
#define NTILES  16             // TSTEPS / TT
#define ROW4    7              // float4s per smem row (6 data + 1 pad) -> conflict-free LDS.128
#define TILE4   (EPB * ROW4)   // float4s per tile buffer (896)
#define TILEF   (TILE4 * 4)    // floats per tile buffer (3584)

static __device__ float g_partial[NB];
static __device__ unsigned int g_count = 0;

__device__ __forceinline__ float tanha(float x) {
    float y;
    asm("tanh.approx.f32 %0, %1;" : "=f"(y) : "f"(x));
    return y;
}
__device__ __forceinline__ void cp_async16(uint32_t dst, const float4* src) {
    asm volatile("cp.async.cg.shared.global [%0], [%1], 16;" :: "r"(dst), "l"(src));
}

struct Elem {
    // rotation basis (kept for target rotation at the end)
    float b1x, b1y, b1z, b2x, b2y, b2z, c3x, c3y, c3z;
    // folded input weights (i,f,o rows pre-scaled by 0.5 for sigmoid-via-tanh)
    float wp[4][3];
    // state + head accumulators
    float h, c;
    float am0, am1, am2, av0, av1, av2, av3, av4, av5;
};

__device__ __forceinline__ void init_elem(Elem& E, const float* __restrict__ hist,
                                          const float* __restrict__ h0,
                                          const float* __restrict__ c0,
                                          const float* wih, int b)
{
    const float4* xr = reinterpret_cast<const float4*>(hist + (size_t)b * (TSTEPS * 3));
    float4 r93 = xr[93];
    float4 r94 = xr[94];
    float4 r95 = xr[95];

    float v1x = r95.y, v1y = r95.z, v1z = r95.w;   // t = 127
    float v2x = r94.z, v2y = r94.w, v2z = r95.x;   // t = 126
    float v3x = r93.w, v3y = r94.x, v3z = r94.y;   // t = 125

    float n1 = rsqrtf(v1x*v1x + v1y*v1y + v1z*v1z);
    E.b1x = v1x*n1; E.b1y = v1y*n1; E.b1z = v1z*n1;

    float p  = v2x*E.b1x + v2y*E.b1y + v2z*E.b1z;
    float a2x = v2x - p*E.b1x, a2y = v2y - p*E.b1y, a2z = v2z - p*E.b1z;
    float n2 = rsqrtf(a2x*a2x + a2y*a2y + a2z*a2z);
    E.b2x = a2x*n2; E.b2y = a2y*n2; E.b2z = a2z*n2;

    float b3x = E.b1y*E.b2z - E.b1z*E.b2y;
    float b3y = E.b1z*E.b2x - E.b1x*E.b2z;
    float b3z = E.b1x*E.b2y - E.b1y*E.b2x;

    float sgn = (v3x*b3x + v3y*b3y + v3z*b3z) > 0.0f ? 1.0f : -1.0f;
    E.c3x = sgn*b3x; E.c3y = sgn*b3y; E.c3z = sgn*b3z;

    #pragma unroll
    for (int k = 0; k < 4; ++k) {
        float s = (k == 2) ? 1.0f : 0.5f;   // fold sigmoid's x/2 into i,f,o rows
        E.wp[k][0] = s * (wih[k*3+0]*E.b1x + wih[k*3+1]*E.b2x + wih[k*3+2]*E.c3x);
        E.wp[k][1] = s * (wih[k*3+0]*E.b1y + wih[k*3+1]*E.b2y + wih[k*3+2]*E.c3y);
        E.wp[k][2] = s * (wih[k*3+0]*E.b1z + wih[k*3+1]*E.b2z + wih[k*3+2]*E.c3z);
    }
    E.h = h0[b]; E.c = c0[b];
    E.am0 = E.am1 = E.am2 = 0.f;
    E.av0 = E.av1 = E.av2 = E.av3 = E.av4 = E.av5 = 0.f;
}

__device__ __forceinline__ void step_elem(Elem& E, float x0, float x1, float x2,
                                          const float* wh, const float* bb,
                                          float4 w0, float4 w1, float w8)
{
    // gates: i,f,o pre-scaled by 0.5 (sigmoid via tanh), g unscaled
    float xp0 = fmaf(x0, E.wp[0][0], fmaf(x1, E.wp[0][1], fmaf(x2, E.wp[0][2], bb[0])));
    float xp1 = fmaf(x0, E.wp[1][0], fmaf(x1, E.wp[1][1], fmaf(x2, E.wp[1][2], bb[1])));
    float xp2 = fmaf(x0, E.wp[2][0], fmaf(x1, E.wp[2][1], fmaf(x2, E.wp[2][2], bb[2])));
    float xp3 = fmaf(x0, E.wp[3][0], fmaf(x1, E.wp[3][1], fmaf(x2, E.wp[3][2], bb[3])));

    float gi = fmaf(E.h, wh[0], xp0);
    float gf = fmaf(E.h, wh[1], xp1);
    float gg = fmaf(E.h, wh[2], xp2);
    float go = fmaf(E.h, wh[3], xp3);

    float si = fmaf(tanha(gi), 0.5f, 0.5f);
    float sf = fmaf(tanha(gf), 0.5f, 0.5f);
    float so = fmaf(tanha(go), 0.5f, 0.5f);
    float tg = tanha(gg);

    E.c = fmaf(sf, E.c, si * tg);
    float h = so * tanha(E.c);
    E.h = h;

    E.am0 = fmaf(h, w0.x, E.am0);
    E.am1 = fmaf(h, w0.y, E.am1);
    E.am2 = fmaf(h, w0.z, E.am2);
    E.av0 = fmaf(h, w0.w, E.av0);
    E.av1 = fmaf(h, w1.x, E.av1);
    E.av2 = fmaf(h, w1.y, E.av2);
    E.av3 = fmaf(h, w1.z, E.av3);
    E.av4 = fmaf(h, w1.w, E.av4);
    E.av5 = fmaf(h, w8,   E.av5);
}

__device__ __forceinline__ float finish_elem(const Elem& E,
                                             const float* __restrict__ target,
                                             const float* __restrict__ bm,
                                             const float* __restrict__ bv, int b)
{
    float m0 = E.am0 + bm[0], m1 = E.am1 + bm[1], m2 = E.am2 + bm[2];
    float e0 = E.av0 + bv[0], e1 = E.av1 + bv[1], e2 = E.av2 + bv[2];
    float e3 = E.av3 + bv[3], e4 = E.av4 + bv[4], e5 = E.av5 + bv[5];

    float tx = target[b*3+0], ty = target[b*3+1], tz = target[b*3+2];
    float rt0 = tx*E.b1x + ty*E.b1y + tz*E.b1z;
    float rt1 = tx*E.b2x + ty*E.b2y + tz*E.b2z;
    float rt2 = tx*E.c3x + ty*E.c3y + tz*E.c3z;

    float d0 = m0 - rt0, d1 = m1 - rt1, d2 = m2 - rt2;

    float z0 = d0;
    float z1 = d1 - e0 * z0;
    float z2 = d2 - e1 * z0 - e2 * z1;

    float quad = z0*z0*__expf(-e3) + z1*z1*__expf(-e4) + z2*z2*__expf(-e5);
    return 0.5f * (__expf(e3) + __expf(e4) + __expf(e5) + quad);
}

__global__ __launch_bounds__(NT)
void recdyn_kernel(const float* __restrict__ hist,
                   const float* __restrict__ h0,
                   const float* __restrict__ c0,
                   const float* __restrict__ target,
                   const float* __restrict__ Wih,
                   const float* __restrict__ Whh,
                   const float* __restrict__ bih,
                   const float* __restrict__ bhh,
                   const float* __restrict__ Wm,
                   const float* __restrict__ bm,
                   const float* __restrict__ Wv,
                   const float* __restrict__ bv,
                   float* __restrict__ out)
{
    __shared__ float sw[TSTEPS * 12];     // head weights transposed: [Wm0..2, Wv0..5, pad3]
    __shared__ float sred[NT];
    __shared__ float sbuf[2 * TILEF];     // double-buffered x tiles (128 rows each)
    __shared__ int slast;

    const int tid = threadIdx.x;
    const int bA  = blockIdx.x * EPB + tid;        // element A
    const int bB  = bA + NT;                       // element B

    for (int i = tid; i < TSTEPS * 12; i += NT) {
        int t = i / 12, j = i % 12;
        float v = 0.0f;
        if (j < 3)      v = Wm[j * TSTEPS + t];
        else if (j < 9) v = Wv[(j - 3) * TSTEPS + t];
        sw[i] = v;
    }

    // ---- cp.async staging: 768 f4 slots/tile over 64 threads = 12 each ----
    const int seg0 = tid / 6;
    const int q0   = tid - seg0 * 6;
    const float4* gbase = reinterpret_cast<const float4*>(hist) + (size_t)blockIdx.x * EPB * 96;
    const uint32_t sbuf_u32 = (uint32_t)__cvta_generic_to_shared(sbuf);

    {
        int s = seg0, qq = q0;
        #pragma unroll
        for (int k = 0; k < 12; ++k) {
            cp_async16(sbuf_u32 + (uint32_t)(s * ROW4 + qq) * 16u,
                       gbase + (size_t)s * 96 + qq);
            s += 10; qq += 4; if (qq >= 6) { qq -= 6; ++s; }
        }
        asm volatile("cp.async.commit_group;");
    }

    float wihr[12];
    #pragma unroll
    for (int k = 0; k < 12; ++k) wihr[k] = Wih[k];

    Elem A, B;
    init_elem(A, hist, h0, c0, wihr, bA);
    init_elem(B, hist, h0, c0, wihr, bB);

    float wh[4], bb[4];
    #pragma unroll
    for (int k = 0; k < 4; ++k) {
        float s = (k == 2) ? 1.0f : 0.5f;
        wh[k] = s * Whh[k];
        bb[k] = s * (bih[k] + bhh[k]);
    }

    for (int g = 0; g < NTILES; ++g) {
        if (g + 1 < NTILES) {
            uint32_t dstb = sbuf_u32 + (uint32_t)(((g + 1) & 1) * TILEF) * 4u;
            const float4* src = gbase + (g + 1) * 6;
            int s = seg0, qq = q0;
            #pragma unroll
            for (int k = 0; k < 12; ++k) {
                cp_async16(dstb + (uint32_t)(s * ROW4 + qq) * 16u,
                           src + (size_t)s * 96 + qq);
                s += 10; qq += 4; if (qq >= 6) { qq -= 6; ++s; }
            }
            asm volatile("cp.async.commit_group;");
            asm volatile("cp.async.wait_group 1;");
        } else {
            asm volatile("cp.async.wait_group 0;");
        }
        __syncthreads();

        const float4* base4 = reinterpret_cast<const float4*>(sbuf + (g & 1) * TILEF);
        const float4* rowA = base4 + tid * ROW4;
        const float4* rowB = base4 + (tid + NT) * ROW4;
        const float* swt = sw + g * TT * 12;

        #pragma unroll
        for (int half = 0; half < 2; ++half) {
            float4 a0 = rowA[half*3 + 0];
            float4 a1 = rowA[half*3 + 1];
            float4 a2 = rowA[half*3 + 2];
            float4 c0v = rowB[half*3 + 0];
            float4 c1v = rowB[half*3 + 1];
            float4 c2v = rowB[half*3 + 2];
            float xsA[12] = {a0.x,a0.y,a0.z,a0.w, a1.x,a1.y,a1.z,a1.w, a2.x,a2.y,a2.z,a2.w};
            float xsB[12] = {c0v.x,c0v.y,c0v.z,c0v.w, c1v.x,c1v.y,c1v.z,c1v.w, c2v.x,c2v.y,c2v.z,c2v.w};
            #pragma unroll
            for (int k = 0; k < 4; ++k) {
                const int tl = half * 4 + k;
                const float* wr = swt + tl * 12;
                const float4* wv4 = reinterpret_cast<const float4*>(wr);
                float4 w0 = wv4[0];
                float4 w1 = wv4[1];
                float  w8 = wr[8];

                step_elem(A, xsA[3*k+0], xsA[3*k+1], xsA[3*k+2], wh, bb, w0, w1, w8);
                step_elem(B, xsB[3*k+0], xsB[3*k+1], xsB[3*k+2], wh, bb, w0, w1, w8);
            }
        }
        __syncthreads();
    }

    float val = finish_elem(A, target, bm, bv, bA)
              + finish_elem(B, target, bm, bv, bB);

    // ---- block tree reduction (deterministic) ----
    sred[tid] = val;
    __syncthreads();
    #pragma unroll
    for (int off = NT/2; off > 0; off >>= 1) {
        if (tid < off) sred[tid] += sred[tid + off];
        __syncthreads();
    }

    // ---- last-block grid reduction (deterministic fixed order) ----
    if (tid == 0) {
        g_partial[blockIdx.x] = sred[0];
        __threadfence();
        unsigned int n = atomicAdd(&g_count, 1u);
        slast = (n == NB - 1) ? 1 : 0;
    }
    __syncthreads();

    if (slast) {
        float s = 0.0f;
        #pragma unroll
        for (int k = 0; k < NB / NT; ++k)
            s += __ldcg(&g_partial[tid * (NB / NT) + k]);
        sred[tid] = s;
        __syncthreads();
        #pragma unroll
        for (int off = NT/2; off > 0; off >>= 1) {
            if (tid < off) sred[tid] += sred[tid + off];
            __syncthreads();
        }
        if (tid == 0) {
            out[0] = sred[0] * (1.0f / 65536.0f);
            g_count = 0;   // reset for next graph replay
        }
    }
}

extern "C" void kernel_launch(void* const* d_in, const int* in_sizes, int n_in,
                              void* d_out, int out_size)
{
    const float* hist   = (const float*)d_in[0];
    const float* h0     = (const float*)d_in[1];
    const float* c0     = (const float*)d_in[2];
    const float* target = (const float*)d_in[3];
    const float* Wih    = (const float*)d_in[4];
    const float* Whh    = (const float*)d_in[5];
    const float* bih    = (const float*)d_in[6];
    const float* bhh    = (const float*)d_in[7];
    const float* Wm     = (const float*)d_in[8];
    const float* bm     = (const float*)d_in[9];
    const float* Wv     = (const float*)d_in[10];
    const float* bv     = (const float*)d_in[11];

    recdyn_kernel<<<NB, NT>>>(hist, h0, c0, target,
                              Wih, Whh, bih, bhh, Wm, bm, Wv, bv,
                              (float*)d_out);
}

// round 6
// speedup vs baseline: 1.0068x; 1.0068x over previous
#include <cuda_runtime.h>
#include <math.h>
#include <stdint.h>

#define NT      64             // threads per block
#define EPB     128            // batch elements per block (2 per thread: A=tid, B=tid+64)
#define NB      512            // 65536 / EPB
#define TSTEPS  128
#define TT      8              // timesteps per tile
#define NTILES  16             // TSTEPS / TT
#define ROW4    7              // float4s per smem row (6 data + 1 pad) -> conflict-free LDS.128
#define TILE4   (EPB * ROW4)   // 896 float4 per tile buffer
#define TILEF   (TILE4 * 4)    // 3584 floats per tile buffer

typedef unsigned long long u64;

static __device__ float g_partial[NB];
static __device__ unsigned int g_count = 0;

__device__ __forceinline__ float tanha(float x) {
    float y;
    asm("tanh.approx.f32 %0, %1;" : "=f"(y) : "f"(x));
    return y;
}
__device__ __forceinline__ u64 pk(float lo, float hi) {
    u64 d; asm("mov.b64 %0, {%1, %2};" : "=l"(d) : "f"(lo), "f"(hi)); return d;
}
__device__ __forceinline__ void upk(float& lo, float& hi, u64 v) {
    asm("mov.b64 {%0, %1}, %2;" : "=f"(lo), "=f"(hi) : "l"(v));
}
__device__ __forceinline__ u64 fma2(u64 a, u64 b, u64 c) {
    u64 d; asm("fma.rn.f32x2 %0, %1, %2, %3;" : "=l"(d) : "l"(a), "l"(b), "l"(c)); return d;
}
__device__ __forceinline__ void cp_async16(uint32_t dst, const float4* src) {
    asm volatile("cp.async.cg.shared.global [%0], [%1], 16;" :: "r"(dst), "l"(src));
}

struct Basis { float b1x,b1y,b1z,b2x,b2y,b2z,c3x,c3y,c3z; };

__device__ __forceinline__ void make_basis(Basis& E, const float* __restrict__ hist, int b)
{
    const float4* xr = reinterpret_cast<const float4*>(hist + (size_t)b * (TSTEPS * 3));
    float4 r93 = xr[93];
    float4 r94 = xr[94];
    float4 r95 = xr[95];

    float v1x = r95.y, v1y = r95.z, v1z = r95.w;   // t = 127
    float v2x = r94.z, v2y = r94.w, v2z = r95.x;   // t = 126
    float v3x = r93.w, v3y = r94.x, v3z = r94.y;   // t = 125

    float n1 = rsqrtf(v1x*v1x + v1y*v1y + v1z*v1z);
    E.b1x = v1x*n1; E.b1y = v1y*n1; E.b1z = v1z*n1;

    float p  = v2x*E.b1x + v2y*E.b1y + v2z*E.b1z;
    float a2x = v2x - p*E.b1x, a2y = v2y - p*E.b1y, a2z = v2z - p*E.b1z;
    float n2 = rsqrtf(a2x*a2x + a2y*a2y + a2z*a2z);
    E.b2x = a2x*n2; E.b2y = a2y*n2; E.b2z = a2z*n2;

    float b3x = E.b1y*E.b2z - E.b1z*E.b2y;
    float b3y = E.b1z*E.b2x - E.b1x*E.b2z;
    float b3z = E.b1x*E.b2y - E.b1y*E.b2x;

    float sgn = (v3x*b3x + v3y*b3y + v3z*b3z) > 0.0f ? 1.0f : -1.0f;
    E.c3x = sgn*b3x; E.c3y = sgn*b3y; E.c3z = sgn*b3z;
}

__device__ __forceinline__ float finish_elem(const Basis& E,
                                             const float* am, const float* av,
                                             const float* __restrict__ target,
                                             const float* __restrict__ bm,
                                             const float* __restrict__ bv, int b)
{
    float m0 = am[0] + bm[0], m1 = am[1] + bm[1], m2 = am[2] + bm[2];
    float e0 = av[0] + bv[0], e1 = av[1] + bv[1], e2 = av[2] + bv[2];
    float e3 = av[3] + bv[3], e4 = av[4] + bv[4], e5 = av[5] + bv[5];

    float tx = target[b*3+0], ty = target[b*3+1], tz = target[b*3+2];
    float rt0 = tx*E.b1x + ty*E.b1y + tz*E.b1z;
    float rt1 = tx*E.b2x + ty*E.b2y + tz*E.b2z;
    float rt2 = tx*E.c3x + ty*E.c3y + tz*E.c3z;

    float d0 = m0 - rt0, d1 = m1 - rt1, d2 = m2 - rt2;

    float z0 = d0;
    float z1 = d1 - e0 * z0;
    float z2 = d2 - e1 * z0 - e2 * z1;

    float quad = z0*z0*__expf(-e3) + z1*z1*__expf(-e4) + z2*z2*__expf(-e5);
    return 0.5f * (__expf(e3) + __expf(e4) + __expf(e5) + quad);
}

__global__ __launch_bounds__(NT)
void recdyn_kernel(const float* __restrict__ hist,
                   const float* __restrict__ h0,
                   const float* __restrict__ c0,
                   const float* __restrict__ target,
                   const float* __restrict__ Wih,
                   const float* __restrict__ Whh,
                   const float* __restrict__ bih,
                   const float* __restrict__ bhh,
                   const float* __restrict__ Wm,
                   const float* __restrict__ bm,
                   const float* __restrict__ Wv,
                   const float* __restrict__ bv,
                   float* __restrict__ out)
{
    // head weights pre-duplicated as (w,w) f32x2 pairs: 10 u64 per timestep (9 used)
    __shared__ __align__(16) u64 sw2[TSTEPS * 10];
    __shared__ float sred[NT];
    __shared__ float sbuf[2 * TILEF];
    __shared__ int slast;

    const int tid = threadIdx.x;
    const int bA  = blockIdx.x * EPB + tid;
    const int bB  = bA + NT;

    // ---- stage duplicated head weights ----
    for (int i = tid; i < TSTEPS * 9; i += NT) {
        int t = i / 9, j = i % 9;
        float w = (j < 3) ? Wm[j * TSTEPS + t] : Wv[(j - 3) * TSTEPS + t];
        reinterpret_cast<float2*>(sw2)[t * 10 + j] = make_float2(w, w);
    }

    // ---- cp.async staging: 768 f4 slots/tile over 64 threads = 12 each ----
    const int seg0 = tid / 6;
    const int q0   = tid - seg0 * 6;
    const float4* gbase = reinterpret_cast<const float4*>(hist) + (size_t)blockIdx.x * EPB * 96;
    const uint32_t sbuf_u32 = (uint32_t)__cvta_generic_to_shared(sbuf);

    {
        int s = seg0, qq = q0;
        #pragma unroll
        for (int k = 0; k < 12; ++k) {
            cp_async16(sbuf_u32 + (uint32_t)(s * ROW4 + qq) * 16u,
                       gbase + (size_t)s * 96 + qq);
            s += 10; qq += 4; if (qq >= 6) { qq -= 6; ++s; }
        }
        asm volatile("cp.async.commit_group;");
    }

    // ---- per-element rotation bases + folded input weights (packed A|B) ----
    Basis A, B;
    make_basis(A, hist, bA);
    make_basis(B, hist, bB);

    float wihr[12];
    #pragma unroll
    for (int k = 0; k < 12; ++k) wihr[k] = Wih[k];

    u64 wpP[4][3];   // packed (A,B) folded input weights; i,f,o rows pre-scaled by 0.5
    #pragma unroll
    for (int k = 0; k < 4; ++k) {
        float s = (k == 2) ? 1.0f : 0.5f;
        float aw0 = s * (wihr[k*3+0]*A.b1x + wihr[k*3+1]*A.b2x + wihr[k*3+2]*A.c3x);
        float aw1 = s * (wihr[k*3+0]*A.b1y + wihr[k*3+1]*A.b2y + wihr[k*3+2]*A.c3y);
        float aw2 = s * (wihr[k*3+0]*A.b1z + wihr[k*3+1]*A.b2z + wihr[k*3+2]*A.c3z);
        float bw0 = s * (wihr[k*3+0]*B.b1x + wihr[k*3+1]*B.b2x + wihr[k*3+2]*B.c3x);
        float bw1 = s * (wihr[k*3+0]*B.b1y + wihr[k*3+1]*B.b2y + wihr[k*3+2]*B.c3y);
        float bw2 = s * (wihr[k*3+0]*B.b1z + wihr[k*3+1]*B.b2z + wihr[k*3+2]*B.c3z);
        wpP[k][0] = pk(aw0, bw0);
        wpP[k][1] = pk(aw1, bw1);
        wpP[k][2] = pk(aw2, bw2);
    }

    u64 whP[4], bbP[4];
    #pragma unroll
    for (int k = 0; k < 4; ++k) {
        float s = (k == 2) ? 1.0f : 0.5f;
        float wv_ = s * Whh[k];
        float bv_ = s * (bih[k] + bhh[k]);
        whP[k] = pk(wv_, wv_);
        bbP[k] = pk(bv_, bv_);
    }

    float hA = h0[bA], cA = c0[bA];
    float hB = h0[bB], cB = c0[bB];
    u64 acc[9];
    #pragma unroll
    for (int j = 0; j < 9; ++j) acc[j] = pk(0.0f, 0.0f);

    for (int g = 0; g < NTILES; ++g) {
        if (g + 1 < NTILES) {
            uint32_t dstb = sbuf_u32 + (uint32_t)(((g + 1) & 1) * TILEF) * 4u;
            const float4* src = gbase + (g + 1) * 6;
            int s = seg0, qq = q0;
            #pragma unroll
            for (int k = 0; k < 12; ++k) {
                cp_async16(dstb + (uint32_t)(s * ROW4 + qq) * 16u,
                           src + (size_t)s * 96 + qq);
                s += 10; qq += 4; if (qq >= 6) { qq -= 6; ++s; }
            }
            asm volatile("cp.async.commit_group;");
            asm volatile("cp.async.wait_group 1;");
        } else {
            asm volatile("cp.async.wait_group 0;");
        }
        __syncthreads();

        const float4* base4 = reinterpret_cast<const float4*>(sbuf + (g & 1) * TILEF);
        const float4* rowA = base4 + tid * ROW4;
        const float4* rowB = base4 + (tid + NT) * ROW4;
        const u64* swt = sw2 + g * TT * 10;

        #pragma unroll
        for (int half = 0; half < 2; ++half) {
            float4 a0 = rowA[half*3 + 0];
            float4 a1 = rowA[half*3 + 1];
            float4 a2 = rowA[half*3 + 2];
            float4 e0v = rowB[half*3 + 0];
            float4 e1v = rowB[half*3 + 1];
            float4 e2v = rowB[half*3 + 2];
            float xsA[12] = {a0.x,a0.y,a0.z,a0.w, a1.x,a1.y,a1.z,a1.w, a2.x,a2.y,a2.z,a2.w};
            float xsB[12] = {e0v.x,e0v.y,e0v.z,e0v.w, e1v.x,e1v.y,e1v.z,e1v.w, e2v.x,e2v.y,e2v.z,e2v.w};

            #pragma unroll
            for (int k = 0; k < 4; ++k) {
                const int tl = half * 4 + k;
                u64 X0 = pk(xsA[3*k+0], xsB[3*k+0]);
                u64 X1 = pk(xsA[3*k+1], xsB[3*k+1]);
                u64 X2 = pk(xsA[3*k+2], xsB[3*k+2]);
                u64 H2 = pk(hA, hB);

                u64 gi2 = fma2(H2, whP[0], fma2(X0, wpP[0][0], fma2(X1, wpP[0][1], fma2(X2, wpP[0][2], bbP[0]))));
                u64 gf2 = fma2(H2, whP[1], fma2(X0, wpP[1][0], fma2(X1, wpP[1][1], fma2(X2, wpP[1][2], bbP[1]))));
                u64 gg2 = fma2(H2, whP[2], fma2(X0, wpP[2][0], fma2(X1, wpP[2][1], fma2(X2, wpP[2][2], bbP[2]))));
                u64 go2 = fma2(H2, whP[3], fma2(X0, wpP[3][0], fma2(X1, wpP[3][1], fma2(X2, wpP[3][2], bbP[3]))));

                float giA, giB, gfA, gfB, ggA, ggB, goA, goB;
                upk(giA, giB, gi2);
                upk(gfA, gfB, gf2);
                upk(ggA, ggB, gg2);
                upk(goA, goB, go2);

                float siA = fmaf(tanha(giA), 0.5f, 0.5f);
                float sfA = fmaf(tanha(gfA), 0.5f, 0.5f);
                float soA = fmaf(tanha(goA), 0.5f, 0.5f);
                float tgA = tanha(ggA);
                float siB = fmaf(tanha(giB), 0.5f, 0.5f);
                float sfB = fmaf(tanha(gfB), 0.5f, 0.5f);
                float soB = fmaf(tanha(goB), 0.5f, 0.5f);
                float tgB = tanha(ggB);

                cA = fmaf(sfA, cA, siA * tgA);
                cB = fmaf(sfB, cB, siB * tgB);
                hA = soA * tanha(cA);
                hB = soB * tanha(cB);

                u64 Hn = pk(hA, hB);
                const ulonglong2* wr = reinterpret_cast<const ulonglong2*>(swt + tl * 10);
                ulonglong2 w01 = wr[0];
                ulonglong2 w23 = wr[1];
                ulonglong2 w45 = wr[2];
                ulonglong2 w67 = wr[3];
                u64        w8  = (swt + tl * 10)[8];

                acc[0] = fma2(Hn, w01.x, acc[0]);
                acc[1] = fma2(Hn, w01.y, acc[1]);
                acc[2] = fma2(Hn, w23.x, acc[2]);
                acc[3] = fma2(Hn, w23.y, acc[3]);
                acc[4] = fma2(Hn, w45.x, acc[4]);
                acc[5] = fma2(Hn, w45.y, acc[5]);
                acc[6] = fma2(Hn, w67.x, acc[6]);
                acc[7] = fma2(Hn, w67.y, acc[7]);
                acc[8] = fma2(Hn, w8,    acc[8]);
            }
        }
        __syncthreads();
    }

    // ---- unpack accumulators, finish both elements ----
    float amA[3], avA[6], amB[3], avB[6];
    upk(amA[0], amB[0], acc[0]);
    upk(amA[1], amB[1], acc[1]);
    upk(amA[2], amB[2], acc[2]);
    upk(avA[0], avB[0], acc[3]);
    upk(avA[1], avB[1], acc[4]);
    upk(avA[2], avB[2], acc[5]);
    upk(avA[3], avB[3], acc[6]);
    upk(avA[4], avB[4], acc[7]);
    upk(avA[5], avB[5], acc[8]);

    float val = finish_elem(A, amA, avA, target, bm, bv, bA)
              + finish_elem(B, amB, avB, target, bm, bv, bB);

    // ---- block tree reduction (deterministic) ----
    sred[tid] = val;
    __syncthreads();
    #pragma unroll
    for (int off = NT/2; off > 0; off >>= 1) {
        if (tid < off) sred[tid] += sred[tid + off];
        __syncthreads();
    }

    // ---- last-block grid reduction (deterministic fixed order) ----
    if (tid == 0) {
        g_partial[blockIdx.x] = sred[0];
        __threadfence();
        unsigned int n = atomicAdd(&g_count, 1u);
        slast = (n == NB - 1) ? 1 : 0;
    }
    __syncthreads();

    if (slast) {
        float s = 0.0f;
        #pragma unroll
        for (int k = 0; k < NB / NT; ++k)
            s += __ldcg(&g_partial[tid * (NB / NT) + k]);
        sred[tid] = s;
        __syncthreads();
        #pragma unroll
        for (int off = NT/2; off > 0; off >>= 1) {
            if (tid < off) sred[tid] += sred[tid + off];
            __syncthreads();
        }
        if (tid == 0) {
            out[0] = sred[0] * (1.0f / 65536.0f);
            g_count = 0;   // reset for next graph replay
        }
    }
}

extern "C" void kernel_launch(void* const* d_in, const int* in_sizes, int n_in,
                              void* d_out, int out_size)
{
    const float* hist   = (const float*)d_in[0];
    const float* h0     = (const float*)d_in[1];
    const float* c0     = (const float*)d_in[2];
    const float* target = (const float*)d_in[3];
    const float* Wih    = (const float*)d_in[4];
    const float* Whh    = (const float*)d_in[5];
    const float* bih    = (const float*)d_in[6];
    const float* bhh    = (const float*)d_in[7];
    const float* Wm     = (const float*)d_in[8];
    const float* bm     = (const float*)d_in[9];
    const float* Wv     = (const float*)d_in[10];
    const float* bv     = (const float*)d_in[11];

    recdyn_kernel<<<NB, NT>>>(hist, h0, c0, target,
                              Wih, Whh, bih, bhh, Wm, bm, Wv, bv,
                              (float*)d_out);
}